// round 9
// baseline (speedup 1.0000x reference)
#include <cuda_runtime.h>

#define NN 512          // batch size
#define DD 128          // feature dim
#define THREADS 1024
#define APC 4           // anchors per CTA
#define NCTA (NN / APC) // 128
#define SRTN 64         // sorted-positives capacity (power of 2)
#define SRTCAP 516      // raw compaction capacity + sentinels

typedef unsigned long long ull;

__device__ float g_partial[NCTA];
__device__ float g_count[NCTA];
__device__ int   g_done = 0;   // reset by finalizing CTA each launch

// Margin scalar may arrive as float32 or float64 device scalar.
__device__ __forceinline__ float read_margin(const void* p) {
    if (p == nullptr) return 0.2f;
    float f = *(const float*)p;
    if (f == 0.0f) return 0.0f;
    float af = fabsf(f);
    if (af > 1e-20f && af < 1e6f) return f;
    return (float)(*(const double*)p);
}

// Packed f32x2 ops (Blackwell PTX).
__device__ __forceinline__ void fma2(ull& d, ull a, ull b) {
    asm("fma.rn.f32x2 %0, %1, %2, %0;" : "+l"(d) : "l"(a), "l"(b));
}
__device__ __forceinline__ ull add2(ull a, ull b) {
    ull r;
    asm("add.rn.f32x2 %0, %1, %2;" : "=l"(r) : "l"(a), "l"(b));
    return r;
}
__device__ __forceinline__ float hsum2(ull v) {
    float lo, hi;
    asm("mov.b64 {%0, %1}, %2;" : "=f"(lo), "=f"(hi) : "l"(v));
    return lo + hi;
}
__device__ __forceinline__ ull pack2(float lo, float hi) {
    ull r;
    asm("mov.b64 %0, {%1, %2};" : "=l"(r) : "f"(lo), "f"(hi));
    return r;
}

// ---------------------------------------------------------------------------
// One fused kernel. CTA = 4 consecutive anchors, 1024 threads (occ 50%),
// grid = 128 -> one wave.
// Phase A: Gram-identity rows; 16 lanes per row; anchors in registers;
//          NO shuffle reduction — partials go through a bank-conflict-free
//          padded SMEM buffer ([64][81], 81 = 17 mod 32), reduced by 320
//          threads, finalized by 256 (overlapped into the next pass).
// Phase B: per-anchor positives sorted (bitonic, 1 warp/anchor) + suffix
//          sums; each (anchor, negative) is a 6-probe binary search + O(1)
//          closed form instead of a ~31-term relu loop. Packed-loop fallback
//          for np > 64 keeps correctness for any label distribution.
// Last-arriving CTA does the deterministic fp64 final reduction.
// ---------------------------------------------------------------------------
__global__ void __launch_bounds__(THREADS, 1)
fused_triplet_kernel(const float* __restrict__ x, const int* __restrict__ L32,
                     const void* __restrict__ mp, float* __restrict__ out,
                     int out_size)
{
    __shared__ float         buf[64][81];        // per-pass partials, 20.3 KB
    __shared__ float         red[64][5];         // per-pass reduced sums
    __shared__ float         d_s[APC][NN];       // distance rows, 8 KB
    __shared__ unsigned char same_s[APC][NN];    // same-label flags, 2 KB
    __shared__ float         srt[APC][SRTCAP];   // compacted/sorted d[pos]+m
    __shared__ float         ss_s[APC][SRTN + 1];// suffix sums of sorted posd
    __shared__ int           lab_s[NN];          // 2 KB
    __shared__ int           np_s[APC];
    __shared__ float         wred[32];
    __shared__ int           flag_s;

    const int tid  = threadIdx.x;
    const int lane = tid & 31;
    const int wid  = tid >> 5;
    const int sub  = tid & 15;     // slice within 16-lane row group
    const int grp  = tid >> 4;     // row-group id 0..63
    const int ib   = blockIdx.x * APC;
    const float m  = read_margin(mp);

    // ---- label dtype detect (int64 => odd 32-bit words all zero) ----
    if (tid == 0) flag_s = 0;
    __syncthreads();
    if (tid < 256 && L32[2 * tid + 1] != 0) flag_s = 1;  // benign OR-race

    // ---- hoist anchors (+eps) into registers: 4 anchors x 2 float4 slices ----
    ull xw[APC][2][2];             // 32 registers of anchor data
    #pragma unroll
    for (int a = 0; a < APC; a++) {
        const float4* xa = (const float4*)(x + (ib + a) * DD);
        #pragma unroll
        for (int i = 0; i < 2; i++) {
            float4 w = xa[sub + 16 * i];
            xw[a][i][0] = pack2(w.x + 1e-6f, w.y + 1e-6f);
            xw[a][i][1] = pack2(w.z + 1e-6f, w.w + 1e-6f);
        }
    }
    // ---- anchor norms in-register (16-lane butterfly, deterministic) ----
    float na[APC];
    #pragma unroll
    for (int a = 0; a < APC; a++) {
        ull nacc = 0;
        #pragma unroll
        for (int i = 0; i < 2; i++) {
            fma2(nacc, xw[a][i][0], xw[a][i][0]);
            fma2(nacc, xw[a][i][1], xw[a][i][1]);
        }
        float s = hsum2(nacc);
        #pragma unroll
        for (int o = 1; o <= 8; o <<= 1) s += __shfl_xor_sync(0xffffffffu, s, o);
        na[a] = s;
    }

    __syncthreads();               // flag_s valid
    const int is64 = (flag_s == 0);
    if (tid < NN) lab_s[tid] = is64 ? L32[2 * tid] : L32[tid];
    __syncthreads();               // lab_s valid

    // ---- same-label flags: 2 anchors per thread-half, done once ----
    {
        int j  = tid & (NN - 1);
        int ah = (tid >> 9) * 2;
        int lj = lab_s[j];
        same_s[ah][j]     = (unsigned char)(lj == lab_s[ib + ah]);
        same_s[ah + 1][j] = (unsigned char)(lj == lab_s[ib + ah + 1]);
    }

    // ---- Phase A: 8 passes; SMEM-partial reduction (no shuffles) ----
    #pragma unroll 1
    for (int p = 0; p < 8; p++) {
        // finalize previous pass's rows (red[] still valid from last sync)
        if (p > 0 && tid < 256) {
            int a = tid >> 6, row = tid & 63;
            float nb  = red[row][0];
            float dot = red[row][1 + a];
            float naa = (a == 0) ? na[0] : (a == 1) ? na[1] : (a == 2) ? na[2] : na[3];
            float d2  = fmaf(-2.f, dot, naa + nb);
            d_s[a][(p - 1) * 64 + row] = sqrtf(fmaxf(d2, 0.f));
        }
        // compute packed partials for this pass
        const int r = p * 64 + grp;
        const ulonglong2* xr = (const ulonglong2*)(x + r * DD);
        ull nb = 0, a0 = 0, a1 = 0, a2 = 0, a3 = 0;
        #pragma unroll
        for (int i = 0; i < 2; i++) {
            ulonglong2 v = xr[sub + 16 * i];  // 256B-contiguous per row group
            fma2(nb, v.x, v.x);         fma2(nb, v.y, v.y);
            fma2(a0, xw[0][i][0], v.x); fma2(a0, xw[0][i][1], v.y);
            fma2(a1, xw[1][i][0], v.x); fma2(a1, xw[1][i][1], v.y);
            fma2(a2, xw[2][i][0], v.x); fma2(a2, xw[2][i][1], v.y);
            fma2(a3, xw[3][i][0], v.x); fma2(a3, xw[3][i][1], v.y);
        }
        float* bp = &buf[grp][5 * sub];   // conflict-free (81-stride, 5-step)
        bp[0] = hsum2(nb);
        bp[1] = hsum2(a0);
        bp[2] = hsum2(a1);
        bp[3] = hsum2(a2);
        bp[4] = hsum2(a3);
        __syncthreads();
        // reduce 16 partials -> red[row][val]
        if (tid < 320) {
            int val = tid >> 6, row = tid & 63;
            float s = 0.f;
            #pragma unroll
            for (int q = 0; q < 16; q++) s += buf[row][5 * q + val];
            red[row][val] = s;
        }
        __syncthreads();
    }
    // finalize last pass + init sort pads
    if (tid < 256) {
        int a = tid >> 6, row = tid & 63;
        float nb  = red[row][0];
        float dot = red[row][1 + a];
        float naa = (a == 0) ? na[0] : (a == 1) ? na[1] : (a == 2) ? na[2] : na[3];
        float d2  = fmaf(-2.f, dot, naa + nb);
        d_s[a][7 * 64 + row] = sqrtf(fmaxf(d2, 0.f));
    }
    if (wid < APC) {                     // pads sort low -> front of ascending
        srt[wid][lane]      = -1e30f;
        srt[wid][lane + 32] = -1e30f;
    }
    __syncthreads();

    // ---- compact positives (warp a -> anchor a), then sort + suffix sums ----
    if (wid < APC) {
        const int a = wid, self = ib + a;
        int cnt = 0;
        #pragma unroll
        for (int base = 0; base < NN; base += 32) {
            int j = base + lane;
            bool pq = same_s[a][j] && (j != self);
            unsigned msk = __ballot_sync(0xffffffffu, pq);
            if (pq) srt[a][cnt + __popc(msk & ((1u << lane) - 1u))] = d_s[a][j] + m;
            cnt += __popc(msk);
        }
        if (lane < 4) srt[a][cnt + lane] = -1e30f;  // fallback sentinels
        if (lane == 0) np_s[a] = cnt;
        __syncwarp();
        if (cnt <= SRTN) {
            // bitonic sort srt[a][0..63] ascending (pads land in front)
            for (int k = 2; k <= SRTN; k <<= 1) {
                for (int j = k >> 1; j > 0; j >>= 1) {
                    #pragma unroll
                    for (int half = 0; half < 2; half++) {
                        int i  = lane + 32 * half;
                        int ix = i ^ j;
                        if (ix > i) {
                            float vi = srt[a][i], vx = srt[a][ix];
                            bool up  = ((i & k) == 0);
                            if ((vi > vx) == up) { srt[a][i] = vx; srt[a][ix] = vi; }
                        }
                    }
                    __syncwarp();
                }
            }
            // suffix sums SS[i] = sum_{t>=i} srt[i] (inclusive), SS[64]=0
            float vhi = srt[a][lane + 32], vlo = srt[a][lane];
            float xh = vhi;
            #pragma unroll
            for (int o = 1; o < 32; o <<= 1) {
                float y = __shfl_down_sync(0xffffffffu, xh, o);
                if (lane + o < 32) xh += y;
            }
            float tot_hi = __shfl_sync(0xffffffffu, xh, 0);
            float xl = vlo;
            #pragma unroll
            for (int o = 1; o < 32; o <<= 1) {
                float y = __shfl_down_sync(0xffffffffu, xl, o);
                if (lane + o < 32) xl += y;
            }
            ss_s[a][lane]      = xl + tot_hi;
            ss_s[a][lane + 32] = xh;
            if (lane == 0) ss_s[a][SRTN] = 0.f;
        }
    }
    __syncthreads();

    // ---- Phase B: thread-half owns anchor pair; g = tid & 511 ----
    const ull SMASK = 0x7FFFFFFF7FFFFFFFULL;
    const ull HALF2 = pack2(0.5f, 0.5f);
    const int g  = tid & (NN - 1);
    const int ah = (tid >> 9) * 2;
    float acc = 0.f;
    #pragma unroll
    for (int aa = 0; aa < 2; aa++) {
        const int a  = ah + aa;
        const int np = np_s[a];
        if (!same_s[a][g]) {
            const float dg = d_s[a][g];
            if (np <= SRTN) {
                if (srt[a][SRTN - 1] > dg) {      // else contribution is 0
                    int i0 = 0;                    // count of entries <= dg
                    #pragma unroll
                    for (int h = 32; h >= 1; h >>= 1)
                        if (srt[a][i0 + h - 1] <= dg) i0 += h;
                    acc += ss_s[a][i0] - (float)(SRTN - i0) * dg;
                }
            } else {
                // fallback: packed relu loop over raw compacted list
                const int npairs = (np + 3) >> 2;
                const ull ndg2 = pack2(-dg, -dg);
                const ull* pv  = (const ull*)&srt[a][0];
                ull s2a = 0, s2b = 0;
                for (int q = 0; q < npairs; q++) {
                    ull v0 = pv[2 * q];
                    ull v1 = pv[2 * q + 1];
                    ull t0 = add2(v0, ndg2);
                    ull t1 = add2(v1, ndg2);
                    ull r0 = add2(t0, t0 & SMASK);
                    ull r1 = add2(t1, t1 & SMASK);
                    fma2(s2a, r0, HALF2);
                    fma2(s2b, r1, HALF2);
                }
                acc += hsum2(s2a) + hsum2(s2b);
            }
        }
    }

    // ---- block reduce (fixed tree) ----
    #pragma unroll
    for (int o = 16; o > 0; o >>= 1) acc += __shfl_xor_sync(0xffffffffu, acc, o);
    if (lane == 0) wred[wid] = acc;
    __syncthreads();
    if (wid == 0) {
        float v = wred[lane];
        #pragma unroll
        for (int o = 16; o > 0; o >>= 1) v += __shfl_xor_sync(0xffffffffu, v, o);
        if (lane == 0) {
            g_partial[blockIdx.x] = v;
            float c = 0.f;
            #pragma unroll
            for (int a = 0; a < APC; a++)
                c += (float)np_s[a] * (float)(NN - 1 - np_s[a]);
            g_count[blockIdx.x] = c;
            __threadfence();
            int t = atomicAdd(&g_done, 1);
            flag_s = (t == NCTA - 1) ? 1 : 0;   // am I the last CTA?
        }
    }
    __syncthreads();

    // ---- last CTA: deterministic fp64 final reduction ----
    if (flag_s && wid == 0) {
        double sd = 0.0, sc = 0.0;
        for (int k = lane; k < NCTA; k += 32) {
            sd += (double)g_partial[k];
            sc += (double)g_count[k];
        }
        #pragma unroll
        for (int o = 16; o > 0; o >>= 1) {
            sd += __shfl_xor_sync(0xffffffffu, sd, o);
            sc += __shfl_xor_sync(0xffffffffu, sc, o);
        }
        if (lane == 0) {
            out[0] = (float)(sd / sc);
            for (int k = 1; k < out_size; k++) out[k] = 0.f;
            __threadfence();
            g_done = 0;   // reset for next graph replay
        }
    }
}

extern "C" void kernel_launch(void* const* d_in, const int* in_sizes, int n_in,
                              void* d_out, int out_size) {
    const float* x      = (const float*)d_in[0];
    const int*   labels = (const int*)d_in[1];
    const void*  margin = (n_in >= 3) ? d_in[2] : nullptr;

    fused_triplet_kernel<<<NCTA, THREADS>>>(x, labels, margin,
                                            (float*)d_out, out_size);
}

// round 10
// speedup vs baseline: 1.0234x; 1.0234x over previous
#include <cuda_runtime.h>

#define NN 512          // batch size
#define DD 128          // feature dim
#define THREADS 1024
#define APC 4           // anchors per CTA
#define NCTA (NN / APC) // 128
#define SRTN 64         // sorted-positives capacity (power of 2)
#define SRTCAP 516      // raw compaction capacity + sentinels

typedef unsigned long long ull;

__device__ float g_partial[NCTA];
__device__ float g_count[NCTA];
__device__ int   g_done = 0;   // reset by finalizing CTA each launch

// Margin scalar may arrive as float32 or float64 device scalar.
__device__ __forceinline__ float read_margin(const void* p) {
    if (p == nullptr) return 0.2f;
    float f = *(const float*)p;
    if (f == 0.0f) return 0.0f;
    float af = fabsf(f);
    if (af > 1e-20f && af < 1e6f) return f;
    return (float)(*(const double*)p);
}

// Packed f32x2 ops (Blackwell PTX).
__device__ __forceinline__ void fma2(ull& d, ull a, ull b) {
    asm("fma.rn.f32x2 %0, %1, %2, %0;" : "+l"(d) : "l"(a), "l"(b));
}
__device__ __forceinline__ ull add2(ull a, ull b) {
    ull r;
    asm("add.rn.f32x2 %0, %1, %2;" : "=l"(r) : "l"(a), "l"(b));
    return r;
}
__device__ __forceinline__ float hsum2(ull v) {
    float lo, hi;
    asm("mov.b64 {%0, %1}, %2;" : "=f"(lo), "=f"(hi) : "l"(v));
    return lo + hi;
}
__device__ __forceinline__ ull pack2(float lo, float hi) {
    ull r;
    asm("mov.b64 %0, {%1, %2};" : "=l"(r) : "f"(lo), "f"(hi));
    return r;
}

// ---------------------------------------------------------------------------
// One fused kernel. CTA = 4 consecutive anchors, 1024 threads (occ 50%),
// grid = 128 -> one wave.
// Phase A (= R8, measured issue 53%): Gram-identity rows, 16 lanes per row,
//   anchors in registers, shuffle reduction, NO extra barriers.
// Phase B (= R9, verified exact): per-anchor positives bitonic-sorted by one
//   warp + suffix sums; each (anchor, negative) is a 6-probe branchless
//   search + closed form. Packed-loop fallback for np > 64.
// Last-arriving CTA does the deterministic fp64 final reduction.
// ---------------------------------------------------------------------------
__global__ void __launch_bounds__(THREADS, 1)
fused_triplet_kernel(const float* __restrict__ x, const int* __restrict__ L32,
                     const void* __restrict__ mp, float* __restrict__ out,
                     int out_size)
{
    __shared__ float         d_s[APC][NN];        // distance rows, 8 KB
    __shared__ unsigned char same_s[APC][NN];     // same-label flags, 2 KB
    __shared__ float         srt[APC][SRTCAP];    // compacted/sorted d[pos]+m
    __shared__ float         ss_s[APC][SRTN + 1]; // suffix sums of sorted posd
    __shared__ int           lab_s[NN];           // 2 KB
    __shared__ int           np_s[APC];
    __shared__ float         wred[32];
    __shared__ int           flag_s;

    const int tid  = threadIdx.x;
    const int lane = tid & 31;
    const int wid  = tid >> 5;
    const int sub  = tid & 15;     // slice within 16-lane row group
    const int grp  = tid >> 4;     // row-group id 0..63
    const int ib   = blockIdx.x * APC;
    const float m  = read_margin(mp);

    // ---- label dtype detect (int64 => odd 32-bit words all zero) ----
    if (tid == 0) flag_s = 0;
    __syncthreads();
    if (tid < 256 && L32[2 * tid + 1] != 0) flag_s = 1;  // benign OR-race

    // ---- hoist anchors (+eps) into registers: 4 anchors x 2 float4 slices ----
    ull xw[APC][2][2];             // 32 registers of anchor data
    #pragma unroll
    for (int a = 0; a < APC; a++) {
        const float4* xa = (const float4*)(x + (ib + a) * DD);
        #pragma unroll
        for (int i = 0; i < 2; i++) {
            float4 w = xa[sub + 16 * i];
            xw[a][i][0] = pack2(w.x + 1e-6f, w.y + 1e-6f);
            xw[a][i][1] = pack2(w.z + 1e-6f, w.w + 1e-6f);
        }
    }
    // ---- anchor norms in-register (16-lane butterfly, deterministic) ----
    float na[APC];
    #pragma unroll
    for (int a = 0; a < APC; a++) {
        ull nacc = 0;
        #pragma unroll
        for (int i = 0; i < 2; i++) {
            fma2(nacc, xw[a][i][0], xw[a][i][0]);
            fma2(nacc, xw[a][i][1], xw[a][i][1]);
        }
        float s = hsum2(nacc);
        #pragma unroll
        for (int o = 1; o <= 8; o <<= 1) s += __shfl_xor_sync(0xffffffffu, s, o);
        na[a] = s;
    }

    __syncthreads();               // flag_s valid
    const int is64 = (flag_s == 0);
    if (tid < NN) lab_s[tid] = is64 ? L32[2 * tid] : L32[tid];
    __syncthreads();               // lab_s valid

    int La[APC];
    #pragma unroll
    for (int a = 0; a < APC; a++) La[a] = lab_s[ib + a];

    // ---- same-label flags: 2 anchors per thread-half, done once ----
    {
        int j  = tid & (NN - 1);
        int ah = (tid >> 9) * 2;
        int lj = lab_s[j];
        same_s[ah][j]     = (unsigned char)(lj == lab_s[ib + ah]);
        same_s[ah + 1][j] = (unsigned char)(lj == lab_s[ib + ah + 1]);
    }
    if (wid < APC) {               // pads sort low -> front of ascending
        srt[wid][lane]      = -1e30f;
        srt[wid][lane + 32] = -1e30f;
    }

    // ---- Phase A: d^2 = na + nb - 2*dot; 8 passes x 64 rows; zero LDS ----
    #pragma unroll
    for (int pass = 0; pass < 8; pass++) {
        const int r = pass * 64 + grp;
        const ulonglong2* xr = (const ulonglong2*)(x + r * DD);
        ull nb = 0, a0 = 0, a1 = 0, a2 = 0, a3 = 0;
        #pragma unroll
        for (int i = 0; i < 2; i++) {
            ulonglong2 v = xr[sub + 16 * i];  // 256B-contiguous per row group
            fma2(nb, v.x, v.x);         fma2(nb, v.y, v.y);
            fma2(a0, xw[0][i][0], v.x); fma2(a0, xw[0][i][1], v.y);
            fma2(a1, xw[1][i][0], v.x); fma2(a1, xw[1][i][1], v.y);
            fma2(a2, xw[2][i][0], v.x); fma2(a2, xw[2][i][1], v.y);
            fma2(a3, xw[3][i][0], v.x); fma2(a3, xw[3][i][1], v.y);
        }
        float snb = hsum2(nb);
        float s0 = hsum2(a0), s1 = hsum2(a1), s2 = hsum2(a2), s3 = hsum2(a3);
        #pragma unroll
        for (int o = 1; o <= 8; o <<= 1) {    // 16-lane butterfly
            snb += __shfl_xor_sync(0xffffffffu, snb, o);
            s0  += __shfl_xor_sync(0xffffffffu, s0, o);
            s1  += __shfl_xor_sync(0xffffffffu, s1, o);
            s2  += __shfl_xor_sync(0xffffffffu, s2, o);
            s3  += __shfl_xor_sync(0xffffffffu, s3, o);
        }
        if (sub == 0) {
            float dots[APC] = {s0, s1, s2, s3};
            #pragma unroll
            for (int a = 0; a < APC; a++) {
                float d2 = fmaf(-2.f, dots[a], na[a] + snb);
                d_s[a][r] = sqrtf(fmaxf(d2, 0.f));   // clamp self-pair cancel
            }
        }
    }
    __syncthreads();

    // ---- compact positives (warp a -> anchor a), then sort + suffix sums ----
    if (wid < APC) {
        const int a = wid, self = ib + a;
        int cnt = 0;
        #pragma unroll
        for (int base = 0; base < NN; base += 32) {
            int j = base + lane;
            bool pq = same_s[a][j] && (j != self);
            unsigned msk = __ballot_sync(0xffffffffu, pq);
            if (pq) srt[a][cnt + __popc(msk & ((1u << lane) - 1u))] = d_s[a][j] + m;
            cnt += __popc(msk);
        }
        if (lane < 4) srt[a][cnt + lane] = -1e30f;  // fallback sentinels
        if (lane == 0) np_s[a] = cnt;
        __syncwarp();
        if (cnt <= SRTN) {
            // bitonic sort srt[a][0..63] ascending (pads land in front)
            for (int k = 2; k <= SRTN; k <<= 1) {
                for (int j = k >> 1; j > 0; j >>= 1) {
                    #pragma unroll
                    for (int half = 0; half < 2; half++) {
                        int i  = lane + 32 * half;
                        int ix = i ^ j;
                        if (ix > i) {
                            float vi = srt[a][i], vx = srt[a][ix];
                            bool up  = ((i & k) == 0);
                            if ((vi > vx) == up) { srt[a][i] = vx; srt[a][ix] = vi; }
                        }
                    }
                    __syncwarp();
                }
            }
            // suffix sums SS[i] = sum_{t>=i} srt[t] (inclusive), SS[64]=0
            float vhi = srt[a][lane + 32], vlo = srt[a][lane];
            float xh = vhi;
            #pragma unroll
            for (int o = 1; o < 32; o <<= 1) {
                float y = __shfl_down_sync(0xffffffffu, xh, o);
                if (lane + o < 32) xh += y;
            }
            float tot_hi = __shfl_sync(0xffffffffu, xh, 0);
            float xl = vlo;
            #pragma unroll
            for (int o = 1; o < 32; o <<= 1) {
                float y = __shfl_down_sync(0xffffffffu, xl, o);
                if (lane + o < 32) xl += y;
            }
            ss_s[a][lane]      = xl + tot_hi;
            ss_s[a][lane + 32] = xh;
            if (lane == 0) ss_s[a][SRTN] = 0.f;
        }
    }
    __syncthreads();

    // ---- Phase B: thread-half owns anchor pair; g = tid & 511 ----
    const ull SMASK = 0x7FFFFFFF7FFFFFFFULL;
    const ull HALF2 = pack2(0.5f, 0.5f);
    const int g  = tid & (NN - 1);
    const int ah = (tid >> 9) * 2;
    float acc = 0.f;
    #pragma unroll
    for (int aa = 0; aa < 2; aa++) {
        const int a  = ah + aa;
        const int np = np_s[a];
        if (!same_s[a][g]) {
            const float dg = d_s[a][g];
            if (np <= SRTN) {
                if (srt[a][SRTN - 1] > dg) {      // else contribution is 0
                    int i0 = 0;                    // count of entries <= dg
                    #pragma unroll
                    for (int h = 32; h >= 1; h >>= 1)
                        if (srt[a][i0 + h - 1] <= dg) i0 += h;
                    acc += ss_s[a][i0] - (float)(SRTN - i0) * dg;
                }
            } else {
                // fallback: packed relu loop over raw compacted list
                const int npairs = (np + 3) >> 2;
                const ull ndg2 = pack2(-dg, -dg);
                const ull* pv  = (const ull*)&srt[a][0];
                ull s2a = 0, s2b = 0;
                for (int q = 0; q < npairs; q++) {
                    ull v0 = pv[2 * q];
                    ull v1 = pv[2 * q + 1];
                    ull t0 = add2(v0, ndg2);
                    ull t1 = add2(v1, ndg2);
                    ull r0 = add2(t0, t0 & SMASK);
                    ull r1 = add2(t1, t1 & SMASK);
                    fma2(s2a, r0, HALF2);
                    fma2(s2b, r1, HALF2);
                }
                acc += hsum2(s2a) + hsum2(s2b);
            }
        }
    }

    // ---- block reduce (fixed tree) ----
    #pragma unroll
    for (int o = 16; o > 0; o >>= 1) acc += __shfl_xor_sync(0xffffffffu, acc, o);
    if (lane == 0) wred[wid] = acc;
    __syncthreads();
    if (wid == 0) {
        float v = wred[lane];
        #pragma unroll
        for (int o = 16; o > 0; o >>= 1) v += __shfl_xor_sync(0xffffffffu, v, o);
        if (lane == 0) {
            g_partial[blockIdx.x] = v;
            float c = 0.f;
            #pragma unroll
            for (int a = 0; a < APC; a++)
                c += (float)np_s[a] * (float)(NN - 1 - np_s[a]);
            g_count[blockIdx.x] = c;
            __threadfence();
            int t = atomicAdd(&g_done, 1);
            flag_s = (t == NCTA - 1) ? 1 : 0;   // am I the last CTA?
        }
    }
    __syncthreads();

    // ---- last CTA: deterministic fp64 final reduction ----
    if (flag_s && wid == 0) {
        double sd = 0.0, sc = 0.0;
        for (int k = lane; k < NCTA; k += 32) {
            sd += (double)g_partial[k];
            sc += (double)g_count[k];
        }
        #pragma unroll
        for (int o = 16; o > 0; o >>= 1) {
            sd += __shfl_xor_sync(0xffffffffu, sd, o);
            sc += __shfl_xor_sync(0xffffffffu, sc, o);
        }
        if (lane == 0) {
            out[0] = (float)(sd / sc);
            for (int k = 1; k < out_size; k++) out[k] = 0.f;
            __threadfence();
            g_done = 0;   // reset for next graph replay
        }
    }
}

extern "C" void kernel_launch(void* const* d_in, const int* in_sizes, int n_in,
                              void* d_out, int out_size) {
    const float* x      = (const float*)d_in[0];
    const int*   labels = (const int*)d_in[1];
    const void*  margin = (n_in >= 3) ? d_in[2] : nullptr;

    fused_triplet_kernel<<<NCTA, THREADS>>>(x, labels, margin,
                                            (float*)d_out, out_size);
}

// round 12
// speedup vs baseline: 1.2689x; 1.2398x over previous
#include <cuda_runtime.h>

#define NN 512          // batch size
#define DD 128          // feature dim
#define THREADS 512
#define APC 4           // anchors per CTA
#define NCTA (NN / APC) // 128
#define NPOS (NN + 4)   // posd row + sentinel pad
#define DPAD 520        // d_s row stride (8 mod 32) -> conflict-free stores

typedef unsigned long long ull;

__device__ float g_partial[NCTA];
__device__ float g_count[NCTA];
__device__ int   g_done = 0;   // reset by finalizing CTA each launch

// Margin scalar may arrive as float32 or float64 device scalar.
__device__ __forceinline__ float read_margin(const void* p) {
    if (p == nullptr) return 0.2f;
    float f = *(const float*)p;
    if (f == 0.0f) return 0.0f;
    float af = fabsf(f);
    if (af > 1e-20f && af < 1e6f) return f;
    return (float)(*(const double*)p);
}

// Packed f32x2 ops (Blackwell PTX).
__device__ __forceinline__ void fma2(ull& d, ull a, ull b) {
    asm("fma.rn.f32x2 %0, %1, %2, %0;" : "+l"(d) : "l"(a), "l"(b));
}
__device__ __forceinline__ ull add2(ull a, ull b) {
    ull r;
    asm("add.rn.f32x2 %0, %1, %2;" : "=l"(r) : "l"(a), "l"(b));
    return r;
}
__device__ __forceinline__ float hsum2(ull v) {
    float lo, hi;
    asm("mov.b64 {%0, %1}, %2;" : "=f"(lo), "=f"(hi) : "l"(v));
    return lo + hi;
}
__device__ __forceinline__ ull pack2(float lo, float hi) {
    ull r;
    asm("mov.b64 %0, {%1, %2};" : "=l"(r) : "f"(lo), "f"(hi));
    return r;
}

// ---------------------------------------------------------------------------
// One fused kernel = R6 (best measured, 18.46us) with the 8-lane reduction
// rewritten as a value-pairing butterfly: 7 SHFL instead of 15, and the
// sqrt+store finalize distributed over 4 lanes instead of serial on one.
// CTA = 4 consecutive anchors, 512 threads.
// ---------------------------------------------------------------------------
__global__ void __launch_bounds__(THREADS, 1)
fused_triplet_kernel(const float* __restrict__ x, const int* __restrict__ L32,
                     const void* __restrict__ mp, float* __restrict__ out,
                     int out_size)
{
    __shared__ float                  d_s[APC][DPAD];   // distance rows (padded)
    __shared__ unsigned char          same_s[APC][NN];  // same-label flags, 2 KB
    __shared__ __align__(16) float    posd[APC][NPOS];  // compacted d[pos]+m
    __shared__ int                    lab_s[NN];        // 2 KB
    __shared__ int                    np_s[APC];
    __shared__ float                  wred[THREADS / 32];
    __shared__ int                    flag_s;

    const int tid  = threadIdx.x;
    const int lane = tid & 31;
    const int wid  = tid >> 5;
    const int sub  = tid & 7;      // slice within 8-lane row group
    const int grp  = tid >> 3;     // row-group id 0..63
    const int ib   = blockIdx.x * APC;
    const float m  = read_margin(mp);

    // ---- label dtype detect (int64 => odd 32-bit words all zero) ----
    if (tid == 0) flag_s = 0;
    __syncthreads();
    if (tid < 256 && L32[2 * tid + 1] != 0) flag_s = 1;  // benign OR-race

    // ---- hoist anchors (+eps) into registers: 4 anchors x 4 float4 slices ----
    ull xw[APC][4][2];             // 64 registers of anchor data
    #pragma unroll
    for (int a = 0; a < APC; a++) {
        const float4* xa = (const float4*)(x + (ib + a) * DD);
        #pragma unroll
        for (int i = 0; i < 4; i++) {
            float4 w = xa[sub + 8 * i];
            xw[a][i][0] = pack2(w.x + 1e-6f, w.y + 1e-6f);
            xw[a][i][1] = pack2(w.z + 1e-6f, w.w + 1e-6f);
        }
    }
    // ---- anchor norms in-register (plain 8-lane butterfly, one-time) ----
    float na0, na1, na2, na3;
    {
        float nv[APC];
        #pragma unroll
        for (int a = 0; a < APC; a++) {
            ull nacc = 0;
            #pragma unroll
            for (int i = 0; i < 4; i++) {
                fma2(nacc, xw[a][i][0], xw[a][i][0]);
                fma2(nacc, xw[a][i][1], xw[a][i][1]);
            }
            float s = hsum2(nacc);
            #pragma unroll
            for (int o = 1; o <= 4; o <<= 1) s += __shfl_xor_sync(0xffffffffu, s, o);
            nv[a] = s;
        }
        na0 = nv[0]; na1 = nv[1]; na2 = nv[2]; na3 = nv[3];
    }

    __syncthreads();               // flag_s valid
    const int is64 = (flag_s == 0);
    lab_s[tid] = is64 ? L32[2 * tid] : L32[tid];
    __syncthreads();               // lab_s valid

    // ---- same-label flags once (hoisted out of the pass loop) ----
    {
        int lj = lab_s[tid];
        same_s[0][tid] = (unsigned char)(lj == lab_s[ib + 0]);
        same_s[1][tid] = (unsigned char)(lj == lab_s[ib + 1]);
        same_s[2][tid] = (unsigned char)(lj == lab_s[ib + 2]);
        same_s[3][tid] = (unsigned char)(lj == lab_s[ib + 3]);
    }

    // per-lane anchor norm for the distributed finalize (lane sub -> anchor sub&3)
    const float naa = ((sub & 3) == 0) ? na0 : ((sub & 3) == 1) ? na1
                    : ((sub & 3) == 2) ? na2 : na3;

    // ---- Phase A: d^2 = na + nb - 2*dot; 8 passes x 64 rows; zero LDS ----
    #pragma unroll
    for (int pass = 0; pass < 8; pass++) {
        const int r = pass * 64 + grp;
        const ulonglong2* xr = (const ulonglong2*)(x + r * DD);
        ull nbp = 0, p0 = 0, p1 = 0, p2 = 0, p3 = 0;
        #pragma unroll
        for (int i = 0; i < 4; i++) {
            ulonglong2 v = xr[sub + 8 * i];   // 128B-contiguous per row group
            fma2(nbp, v.x, v.x);        fma2(nbp, v.y, v.y);
            fma2(p0, xw[0][i][0], v.x); fma2(p0, xw[0][i][1], v.y);
            fma2(p1, xw[1][i][0], v.x); fma2(p1, xw[1][i][1], v.y);
            fma2(p2, xw[2][i][0], v.x); fma2(p2, xw[2][i][1], v.y);
            fma2(p3, xw[3][i][0], v.x); fma2(p3, xw[3][i][1], v.y);
        }
        float nb = hsum2(nbp);
        float a0 = hsum2(p0), a1 = hsum2(p1), a2 = hsum2(p2), a3 = hsum2(p3);

        // value-pairing butterfly: 7 SHFL total (vs 15)
        // step 1 (xor 1): merge (a0,a1) and (a2,a3); nb plain
        {
            float w  = (sub & 1) ? a0 : a1;          // send partner's slot
            float rv = __shfl_xor_sync(0xffffffffu, w, 1);
            if (sub & 1) a1 += rv; else a0 += rv;    // even keeps a0, odd keeps a1
            float w2  = (sub & 1) ? a2 : a3;
            float rv2 = __shfl_xor_sync(0xffffffffu, w2, 1);
            if (sub & 1) a3 += rv2; else a2 += rv2;  // even keeps a2, odd keeps a3
            nb += __shfl_xor_sync(0xffffffffu, nb, 1);
        }
        // step 2 (xor 2): merge (first,second); nb plain
        float fst = (sub & 1) ? a1 : a0;             // live "first" value
        float snd = (sub & 1) ? a3 : a2;             // live "second" value
        {
            float w  = (sub & 2) ? fst : snd;
            float rv = __shfl_xor_sync(0xffffffffu, w, 2);
            if (sub & 2) snd += rv; else fst += rv;  // bit1=0 keeps fst, =1 keeps snd
            nb += __shfl_xor_sync(0xffffffffu, nb, 2);
        }
        // step 3 (xor 4): finish the owned dot; nb plain
        float dot = (sub & 2) ? snd : fst;           // lane sub owns anchor sub&3
        dot += __shfl_xor_sync(0xffffffffu, dot, 4);
        nb  += __shfl_xor_sync(0xffffffffu, nb, 4);

        // distributed finalize: lanes sub 0..3 each store one anchor's row
        if (sub < 4) {
            float d2 = fmaf(-2.f, dot, naa + nb);
            d_s[sub][r] = sqrtf(fmaxf(d2, 0.f));     // clamp self-pair cancel
        }
    }
    __syncthreads();

    // ---- compact positives: warp a compacts anchor a (ballot, fixed order) ----
    if (wid < APC) {
        const int a = wid, self = ib + a;
        int cnt = 0;
        #pragma unroll
        for (int base = 0; base < NN; base += 32) {
            int j = base + lane;
            bool p = same_s[a][j] && (j != self);
            unsigned msk = __ballot_sync(0xffffffffu, p);
            if (p) posd[a][cnt + __popc(msk & ((1u << lane) - 1u))] = d_s[a][j] + m;
            cnt += __popc(msk);
        }
        if (lane < 4) posd[a][cnt + lane] = -1e30f;  // sentinels: exact-0 relu
        if (lane == 0) np_s[a] = cnt;
    }
    __syncthreads();

    // ---- Phase B: thread owns candidate negative g = tid; packed f32x2 ----
    const ull SMASK = 0x7FFFFFFF7FFFFFFFULL;
    const ull HALF2 = pack2(0.5f, 0.5f);
    ull acc2 = 0, acc2b = 0;
    #pragma unroll
    for (int a = 0; a < APC; a++) {
        const int npairs = (np_s[a] + 3) >> 2;   // 4 terms per iteration
        if (!same_s[a][tid]) {
            const float dg = d_s[a][tid];
            const ull  ndg2 = pack2(-dg, -dg);
            const ull* pv = (const ull*)&posd[a][0];
            for (int q = 0; q < npairs; q++) {
                ull v0 = pv[2 * q];
                ull v1 = pv[2 * q + 1];
                ull t0 = add2(v0, ndg2);
                ull t1 = add2(v1, ndg2);
                ull r0 = add2(t0, t0 & SMASK);   // 2*relu, exact
                ull r1 = add2(t1, t1 & SMASK);
                fma2(acc2,  r0, HALF2);
                fma2(acc2b, r1, HALF2);
            }
        }
    }
    float acc = hsum2(acc2) + hsum2(acc2b);

    // ---- block reduce (fixed tree) ----
    #pragma unroll
    for (int o = 16; o > 0; o >>= 1) acc += __shfl_xor_sync(0xffffffffu, acc, o);
    if (lane == 0) wred[wid] = acc;
    __syncthreads();
    if (wid == 0) {
        float v = (lane < THREADS / 32) ? wred[lane] : 0.f;
        #pragma unroll
        for (int o = 8; o > 0; o >>= 1) v += __shfl_xor_sync(0xffffffffu, v, o);
        if (lane == 0) {
            g_partial[blockIdx.x] = v;
            float c = 0.f;
            #pragma unroll
            for (int a = 0; a < APC; a++)
                c += (float)np_s[a] * (float)(NN - 1 - np_s[a]);
            g_count[blockIdx.x] = c;
            __threadfence();
            int t = atomicAdd(&g_done, 1);
            flag_s = (t == NCTA - 1) ? 1 : 0;   // am I the last CTA?
        }
    }
    __syncthreads();

    // ---- last CTA: deterministic fp64 final reduction ----
    if (flag_s && wid == 0) {
        double sd = 0.0, sc = 0.0;
        for (int k = lane; k < NCTA; k += 32) {
            sd += (double)g_partial[k];
            sc += (double)g_count[k];
        }
        #pragma unroll
        for (int o = 16; o > 0; o >>= 1) {
            sd += __shfl_xor_sync(0xffffffffu, sd, o);
            sc += __shfl_xor_sync(0xffffffffu, sc, o);
        }
        if (lane == 0) {
            out[0] = (float)(sd / sc);
            for (int k = 1; k < out_size; k++) out[k] = 0.f;
            __threadfence();
            g_done = 0;   // reset for next graph replay
        }
    }
}

extern "C" void kernel_launch(void* const* d_in, const int* in_sizes, int n_in,
                              void* d_out, int out_size) {
    const float* x      = (const float*)d_in[0];
    const int*   labels = (const int*)d_in[1];
    const void*  margin = (n_in >= 3) ? d_in[2] : nullptr;

    fused_triplet_kernel<<<NCTA, THREADS>>>(x, labels, margin,
                                            (float*)d_out, out_size);
}

// round 13
// speedup vs baseline: 1.2788x; 1.0078x over previous
#include <cuda_runtime.h>

#define NN 512          // batch size
#define DD 128          // feature dim
#define THREADS 512
#define APC 4           // anchors per CTA
#define NCTA (NN / APC) // 128
#define NPOS (NN + 4)   // posd row + sentinel pad
#define DPAD 520        // d_s row stride (8 mod 32) -> conflict-free stores

typedef unsigned long long ull;

__device__ float g_partial[NCTA];
__device__ float g_count[NCTA];
__device__ int   g_done = 0;   // reset by finalizing CTA each launch

// Margin scalar may arrive as float32 or float64 device scalar.
__device__ __forceinline__ float read_margin(const void* p) {
    if (p == nullptr) return 0.2f;
    float f = *(const float*)p;
    if (f == 0.0f) return 0.0f;
    float af = fabsf(f);
    if (af > 1e-20f && af < 1e6f) return f;
    return (float)(*(const double*)p);
}

// Packed f32x2 ops (Blackwell PTX).
__device__ __forceinline__ void fma2(ull& d, ull a, ull b) {
    asm("fma.rn.f32x2 %0, %1, %2, %0;" : "+l"(d) : "l"(a), "l"(b));
}
__device__ __forceinline__ ull add2(ull a, ull b) {
    ull r;
    asm("add.rn.f32x2 %0, %1, %2;" : "=l"(r) : "l"(a), "l"(b));
    return r;
}
__device__ __forceinline__ float hsum2(ull v) {
    float lo, hi;
    asm("mov.b64 {%0, %1}, %2;" : "=f"(lo), "=f"(hi) : "l"(v));
    return lo + hi;
}
__device__ __forceinline__ ull pack2(float lo, float hi) {
    ull r;
    asm("mov.b64 %0, {%1, %2};" : "=l"(r) : "f"(lo), "f"(hi));
    return r;
}

// ---------------------------------------------------------------------------
// One fused kernel = R12 (best measured, 16.54us) with Phase A software-
// pipelined: pass p+1's global loads are issued BEFORE pass p's fma/reduce
// work, so the ~250-cycle L2 latency is covered by ~150+ cycles of
// independent math plus multi-warp overlap. Everything else unchanged.
// CTA = 4 consecutive anchors, 512 threads.
// ---------------------------------------------------------------------------
__global__ void __launch_bounds__(THREADS, 1)
fused_triplet_kernel(const float* __restrict__ x, const int* __restrict__ L32,
                     const void* __restrict__ mp, float* __restrict__ out,
                     int out_size)
{
    __shared__ float                  d_s[APC][DPAD];   // distance rows (padded)
    __shared__ unsigned char          same_s[APC][NN];  // same-label flags, 2 KB
    __shared__ __align__(16) float    posd[APC][NPOS];  // compacted d[pos]+m
    __shared__ int                    lab_s[NN];        // 2 KB
    __shared__ int                    np_s[APC];
    __shared__ float                  wred[THREADS / 32];
    __shared__ int                    flag_s;

    const int tid  = threadIdx.x;
    const int lane = tid & 31;
    const int wid  = tid >> 5;
    const int sub  = tid & 7;      // slice within 8-lane row group
    const int grp  = tid >> 3;     // row-group id 0..63
    const int ib   = blockIdx.x * APC;
    const float m  = read_margin(mp);

    // ---- label dtype detect (int64 => odd 32-bit words all zero) ----
    if (tid == 0) flag_s = 0;
    __syncthreads();
    if (tid < 256 && L32[2 * tid + 1] != 0) flag_s = 1;  // benign OR-race

    // ---- hoist anchors (+eps) into registers: 4 anchors x 4 float4 slices ----
    ull xw[APC][4][2];             // 64 registers of anchor data
    #pragma unroll
    for (int a = 0; a < APC; a++) {
        const float4* xa = (const float4*)(x + (ib + a) * DD);
        #pragma unroll
        for (int i = 0; i < 4; i++) {
            float4 w = xa[sub + 8 * i];
            xw[a][i][0] = pack2(w.x + 1e-6f, w.y + 1e-6f);
            xw[a][i][1] = pack2(w.z + 1e-6f, w.w + 1e-6f);
        }
    }
    // ---- anchor norms in-register (plain 8-lane butterfly, one-time) ----
    float na0, na1, na2, na3;
    {
        float nv[APC];
        #pragma unroll
        for (int a = 0; a < APC; a++) {
            ull nacc = 0;
            #pragma unroll
            for (int i = 0; i < 4; i++) {
                fma2(nacc, xw[a][i][0], xw[a][i][0]);
                fma2(nacc, xw[a][i][1], xw[a][i][1]);
            }
            float s = hsum2(nacc);
            #pragma unroll
            for (int o = 1; o <= 4; o <<= 1) s += __shfl_xor_sync(0xffffffffu, s, o);
            nv[a] = s;
        }
        na0 = nv[0]; na1 = nv[1]; na2 = nv[2]; na3 = nv[3];
    }

    __syncthreads();               // flag_s valid
    const int is64 = (flag_s == 0);
    lab_s[tid] = is64 ? L32[2 * tid] : L32[tid];
    __syncthreads();               // lab_s valid

    // ---- same-label flags once (hoisted out of the pass loop) ----
    {
        int lj = lab_s[tid];
        same_s[0][tid] = (unsigned char)(lj == lab_s[ib + 0]);
        same_s[1][tid] = (unsigned char)(lj == lab_s[ib + 1]);
        same_s[2][tid] = (unsigned char)(lj == lab_s[ib + 2]);
        same_s[3][tid] = (unsigned char)(lj == lab_s[ib + 3]);
    }

    // per-lane anchor norm for the distributed finalize (lane sub -> anchor sub&3)
    const float naa = ((sub & 3) == 0) ? na0 : ((sub & 3) == 1) ? na1
                    : ((sub & 3) == 2) ? na2 : na3;

    // ---- Phase A: pipelined; d^2 = na + nb - 2*dot; 8 passes x 64 rows ----
    ull v0, v1, v2, v3;            // current pass's row slice (prefetched)
    {
        const ulonglong2* xr = (const ulonglong2*)(x + grp * DD);
        ulonglong2 t0 = xr[sub],      t1 = xr[sub + 8];
        ulonglong2 t2 = xr[sub + 16], t3 = xr[sub + 24];
        v0 = t0.x; v1 = t1.x; v2 = t2.x; v3 = t3.x;
        // keep .y halves too: store pairs as two regs each
        // (use arrays for clarity below)
    }
    // Re-do preload with explicit pair storage (8 ull regs: 4 slices x {x,y}).
    ull vx[4], vy[4];
    {
        const ulonglong2* xr = (const ulonglong2*)(x + grp * DD);
        #pragma unroll
        for (int i = 0; i < 4; i++) {
            ulonglong2 t = xr[sub + 8 * i];
            vx[i] = t.x; vy[i] = t.y;
        }
    }
    #pragma unroll
    for (int pass = 0; pass < 8; pass++) {
        const int r = pass * 64 + grp;
        // prefetch next pass FIRST (independent of this pass's math)
        ull nx[4], ny[4];
        if (pass < 7) {
            const ulonglong2* xn = (const ulonglong2*)(x + (r + 64) * DD);
            #pragma unroll
            for (int i = 0; i < 4; i++) {
                ulonglong2 t = xn[sub + 8 * i];
                nx[i] = t.x; ny[i] = t.y;
            }
        }
        // compute with current registers (covers the prefetch latency)
        ull nbp = 0, p0 = 0, p1 = 0, p2 = 0, p3 = 0;
        #pragma unroll
        for (int i = 0; i < 4; i++) {
            fma2(nbp, vx[i], vx[i]);       fma2(nbp, vy[i], vy[i]);
            fma2(p0, xw[0][i][0], vx[i]);  fma2(p0, xw[0][i][1], vy[i]);
            fma2(p1, xw[1][i][0], vx[i]);  fma2(p1, xw[1][i][1], vy[i]);
            fma2(p2, xw[2][i][0], vx[i]);  fma2(p2, xw[2][i][1], vy[i]);
            fma2(p3, xw[3][i][0], vx[i]);  fma2(p3, xw[3][i][1], vy[i]);
        }
        float nb = hsum2(nbp);
        float a0 = hsum2(p0), a1 = hsum2(p1), a2 = hsum2(p2), a3 = hsum2(p3);

        // value-pairing butterfly: 7 SHFL total
        {
            float w  = (sub & 1) ? a0 : a1;
            float rv = __shfl_xor_sync(0xffffffffu, w, 1);
            if (sub & 1) a1 += rv; else a0 += rv;
            float w2  = (sub & 1) ? a2 : a3;
            float rv2 = __shfl_xor_sync(0xffffffffu, w2, 1);
            if (sub & 1) a3 += rv2; else a2 += rv2;
            nb += __shfl_xor_sync(0xffffffffu, nb, 1);
        }
        float fst = (sub & 1) ? a1 : a0;
        float snd = (sub & 1) ? a3 : a2;
        {
            float w  = (sub & 2) ? fst : snd;
            float rv = __shfl_xor_sync(0xffffffffu, w, 2);
            if (sub & 2) snd += rv; else fst += rv;
            nb += __shfl_xor_sync(0xffffffffu, nb, 2);
        }
        float dot = (sub & 2) ? snd : fst;
        dot += __shfl_xor_sync(0xffffffffu, dot, 4);
        nb  += __shfl_xor_sync(0xffffffffu, nb, 4);

        if (sub < 4) {
            float d2 = fmaf(-2.f, dot, naa + nb);
            d_s[sub][r] = sqrtf(fmaxf(d2, 0.f));     // clamp self-pair cancel
        }
        // roll the pipeline
        if (pass < 7) {
            #pragma unroll
            for (int i = 0; i < 4; i++) { vx[i] = nx[i]; vy[i] = ny[i]; }
        }
    }
    __syncthreads();

    // ---- compact positives: warp a compacts anchor a (ballot, fixed order) ----
    if (wid < APC) {
        const int a = wid, self = ib + a;
        int cnt = 0;
        #pragma unroll
        for (int base = 0; base < NN; base += 32) {
            int j = base + lane;
            bool p = same_s[a][j] && (j != self);
            unsigned msk = __ballot_sync(0xffffffffu, p);
            if (p) posd[a][cnt + __popc(msk & ((1u << lane) - 1u))] = d_s[a][j] + m;
            cnt += __popc(msk);
        }
        if (lane < 4) posd[a][cnt + lane] = -1e30f;  // sentinels: exact-0 relu
        if (lane == 0) np_s[a] = cnt;
    }
    __syncthreads();

    // ---- Phase B: thread owns candidate negative g = tid; packed f32x2 ----
    const ull SMASK = 0x7FFFFFFF7FFFFFFFULL;
    const ull HALF2 = pack2(0.5f, 0.5f);
    ull acc2 = 0, acc2b = 0;
    #pragma unroll
    for (int a = 0; a < APC; a++) {
        const int npairs = (np_s[a] + 3) >> 2;   // 4 terms per iteration
        if (!same_s[a][tid]) {
            const float dg = d_s[a][tid];
            const ull  ndg2 = pack2(-dg, -dg);
            const ull* pv = (const ull*)&posd[a][0];
            for (int q = 0; q < npairs; q++) {
                ull w0 = pv[2 * q];
                ull w1 = pv[2 * q + 1];
                ull t0 = add2(w0, ndg2);
                ull t1 = add2(w1, ndg2);
                ull r0 = add2(t0, t0 & SMASK);   // 2*relu, exact
                ull r1 = add2(t1, t1 & SMASK);
                fma2(acc2,  r0, HALF2);
                fma2(acc2b, r1, HALF2);
            }
        }
    }
    float acc = hsum2(acc2) + hsum2(acc2b);

    // ---- block reduce (fixed tree) ----
    #pragma unroll
    for (int o = 16; o > 0; o >>= 1) acc += __shfl_xor_sync(0xffffffffu, acc, o);
    if (lane == 0) wred[wid] = acc;
    __syncthreads();
    if (wid == 0) {
        float v = (lane < THREADS / 32) ? wred[lane] : 0.f;
        #pragma unroll
        for (int o = 8; o > 0; o >>= 1) v += __shfl_xor_sync(0xffffffffu, v, o);
        if (lane == 0) {
            g_partial[blockIdx.x] = v;
            float c = 0.f;
            #pragma unroll
            for (int a = 0; a < APC; a++)
                c += (float)np_s[a] * (float)(NN - 1 - np_s[a]);
            g_count[blockIdx.x] = c;
            __threadfence();
            int t = atomicAdd(&g_done, 1);
            flag_s = (t == NCTA - 1) ? 1 : 0;   // am I the last CTA?
        }
    }
    __syncthreads();

    // ---- last CTA: deterministic fp64 final reduction ----
    if (flag_s && wid == 0) {
        double sd = 0.0, sc = 0.0;
        for (int k = lane; k < NCTA; k += 32) {
            sd += (double)g_partial[k];
            sc += (double)g_count[k];
        }
        #pragma unroll
        for (int o = 16; o > 0; o >>= 1) {
            sd += __shfl_xor_sync(0xffffffffu, sd, o);
            sc += __shfl_xor_sync(0xffffffffu, sc, o);
        }
        if (lane == 0) {
            out[0] = (float)(sd / sc);
            for (int k = 1; k < out_size; k++) out[k] = 0.f;
            __threadfence();
            g_done = 0;   // reset for next graph replay
        }
    }
}

extern "C" void kernel_launch(void* const* d_in, const int* in_sizes, int n_in,
                              void* d_out, int out_size) {
    const float* x      = (const float*)d_in[0];
    const int*   labels = (const int*)d_in[1];
    const void*  margin = (n_in >= 3) ? d_in[2] : nullptr;

    fused_triplet_kernel<<<NCTA, THREADS>>>(x, labels, margin,
                                            (float*)d_out, out_size);
}